// round 10
// baseline (speedup 1.0000x reference)
#include <cuda_runtime.h>
#include <cstdint>

// Problem dims
#define TT    512
#define BB    32
#define DD    512
#define HH    512
#define FEAT  2048
#define G4H   2048   // 4*H

// Output layout (fp32, tuple order: out, h_n, c_n, x, lens_s)
#define OUT_OFF  0
#define HN_OFF   16777216
#define CN_OFF   (16777216 + 32768)
#define X_OFF    (16777216 + 65536)
#define LENS_OFF (X_OFF + 8388608)

#define GSZ       (512*32*2048)        // per-direction G size (floats)
#define WCHUNKS   524288               // frag chunks per weight matrix

// scan smem: h rows padded 576 (16 chunks of 36), g_s 32*36, gate_s 8*168
#define PADH      576
#define HS_FLOATS (32*PADH)
#define GS_OFF    HS_FLOATS
#define GATE_OFF  (HS_FLOATS + 32*36)
#define SCAN_SMEM ((HS_FLOATS + 32*36 + 8*168) * 4)

// ---------------- device scratch ---------------------------------------
__device__ float    g_G[2 * GSZ];          // input-gate preactivations (268MB)
__device__ float    g_hbuf[4 * 16384];     // [dir][pingpong][32][512]
__device__ int      g_order[BB];
__device__ int      g_lens[BB];
__device__ unsigned g_flags[2][64];        // per-dir per-CTA step flags
__device__ uint4    g_wfc[WCHUNKS];        // fc_w   frag-layout (hi/lo tf32)
__device__ uint4    g_wih[2][WCHUNKS];     // w_ih_f / w_ih_b frag-layout

// ---------------- helpers ----------------------------------------------
__device__ __forceinline__ uint32_t f2tf32(float v) {
    uint32_t r;
    asm("cvt.rna.tf32.f32 %0, %1;" : "=r"(r) : "f"(v));
    return r;
}

__device__ __forceinline__ void mma_tf32(float4& c, const uint4& a,
                                         uint32_t b0, uint32_t b1) {
    asm volatile(
        "mma.sync.aligned.m16n8k8.row.col.f32.tf32.tf32.f32 "
        "{%0,%1,%2,%3}, {%4,%5,%6,%7}, {%8,%9}, {%0,%1,%2,%3};"
        : "+f"(c.x), "+f"(c.y), "+f"(c.z), "+f"(c.w)
        : "r"(a.x), "r"(a.y), "r"(a.z), "r"(a.w), "r"(b0), "r"(b1));
}

#define FMA2(acc, a, b) \
    asm("fma.rn.f32x2 %0, %1, %2, %0;" : "+l"(acc) : "l"(a), "l"(b))

__device__ __forceinline__ float sum2(unsigned long long v) {
    float lo, hi;
    asm("mov.b64 {%0,%1}, %2;" : "=f"(lo), "=f"(hi) : "l"(v));
    return lo + hi;
}

__device__ __forceinline__ unsigned long long packf2(float a, float b) {
    unsigned long long u;
    asm("mov.b64 %0, {%1,%2};" : "=l"(u) : "f"(a), "f"(b));
    return u;
}

// ---------------- reset / sort kernel ----------------------------------
__global__ void k_reset(const int* __restrict__ seq_lens,
                        const float* __restrict__ h0,
                        float* __restrict__ out) {
    int tid = threadIdx.x;
    if (tid == 0) {
        unsigned used = 0u;
        for (int pos = 0; pos < BB; pos++) {
            int best = -1, bl = -1;
            for (int i = 0; i < BB; i++) {
                if (used & (1u << i)) continue;
                int L = seq_lens[i];
                if (L > bl) { bl = L; best = i; }
            }
            used |= 1u << best;
            g_order[pos] = best;
            g_lens[pos]  = bl;
            out[LENS_OFF + pos] = (float)bl;
        }
    }
    if (tid < 128) g_flags[tid >> 6][tid & 63] = 0u;
    for (int i = tid; i < 2 * 16384; i += blockDim.x) {
        int dir = i >> 14;
        int r   = i & 16383;
        g_hbuf[(dir * 2 + 0) * 16384 + r] = h0[i];
    }
}

// ---------------- weight pre-conversion to frag layout ------------------
__global__ void __launch_bounds__(256) k_prep(
    const float* __restrict__ fcw, const float* __restrict__ wihf,
    const float* __restrict__ wihb) {
    int z = blockIdx.y;
    const float* src = (z == 0) ? fcw : ((z == 1) ? wihf : wihb);
    uint4* dst = (z == 0) ? g_wfc : g_wih[z - 1];
    int K     = (z == 0) ? FEAT : DD;
    int nKtm1 = (z == 0) ? 63 : 15;
    int nKtsh = (z == 0) ? 6 : 4;

    int c    = blockIdx.x * 256 + threadIdx.x;
    int lane = c & 31;
    int hl   = (c >> 5) & 1;
    int s    = (c >> 6) & 3;
    int q    = (c >> 8) & 3;
    int tile = c >> 10;
    int qt   = tile & nKtm1;
    int r64  = tile >> nKtsh;
    int g    = lane >> 2, tg = lane & 3;
    int m0   = r64 * 64 + s * 16;
    int kk   = qt * 32 + q * 8 + tg;

    float v0 = src[(size_t)(m0 + g)     * K + kk];
    float v1 = src[(size_t)(m0 + g + 8) * K + kk];
    float v2 = src[(size_t)(m0 + g)     * K + kk + 4];
    float v3 = src[(size_t)(m0 + g + 8) * K + kk + 4];
    uint4 o;
    if (hl == 0) {
        o.x = f2tf32(v0); o.y = f2tf32(v1); o.z = f2tf32(v2); o.w = f2tf32(v3);
    } else {
        o.x = f2tf32(v0 - __uint_as_float(f2tf32(v0)));
        o.y = f2tf32(v1 - __uint_as_float(f2tf32(v1)));
        o.z = f2tf32(v2 - __uint_as_float(f2tf32(v2)));
        o.w = f2tf32(v3 - __uint_as_float(f2tf32(v3)));
    }
    dst[c] = o;
}

// ================= MMA GEMMs (A = weights frag-global, B = data rows) ==
__device__ __forceinline__ void sts_b_convert(uint4* Bsm, const float4* braw,
                                              int r, int qp) {
    int xr = (r & 3) ^ ((r >> 2) & 3);
#pragma unroll
    for (int oo = 0; oo < 2; oo++) {
        float f[8];
        f[0] = braw[oo*2].x;   f[1] = braw[oo*2].y;
        f[2] = braw[oo*2].z;   f[3] = braw[oo*2].w;
        f[4] = braw[oo*2+1].x; f[5] = braw[oo*2+1].y;
        f[6] = braw[oo*2+1].z; f[7] = braw[oo*2+1].w;
        uint32_t hi[8], lo[8];
#pragma unroll
        for (int p = 0; p < 8; p++) {
            hi[p] = f2tf32(f[p]);
            lo[p] = f2tf32(f[p] - __uint_as_float(hi[p]));
        }
        int q = qp * 2 + oo;
        int sbase = q * 256 + r * 4;
#pragma unroll
        for (int t2 = 0; t2 < 4; t2++) {
            uint4 ch;
            ch.x = hi[t2]; ch.y = hi[t2 + 4];
            ch.z = lo[t2]; ch.w = lo[t2 + 4];
            Bsm[sbase + (t2 ^ xr)] = ch;
        }
    }
}

__device__ __forceinline__ void mma_ktile(const uint4* As, const uint4* Bsm,
                                          float4 c[2][4], int wm, int wn,
                                          int lane, int g, int tg) {
#pragma unroll
    for (int q = 0; q < 4; q++) {
        uint4 ah[2], al[2], bq[4];
#pragma unroll
        for (int mi = 0; mi < 2; mi++) {
            int s = wm * 2 + mi;
            ah[mi] = As[((q * 4 + s) * 2 + 0) * 32 + lane];
            al[mi] = As[((q * 4 + s) * 2 + 1) * 32 + lane];
        }
#pragma unroll
        for (int ni = 0; ni < 4; ni++) {
            int rr = wn * 32 + ni * 8 + g;
            int sw = tg ^ (rr & 3) ^ ((rr >> 2) & 3);
            bq[ni] = Bsm[q * 256 + rr * 4 + sw];
        }
#pragma unroll
        for (int mi = 0; mi < 2; mi++)
#pragma unroll
            for (int ni = 0; ni < 4; ni++) {
                mma_tf32(c[mi][ni], ah[mi], bq[ni].x, bq[ni].y);
                mma_tf32(c[mi][ni], ah[mi], bq[ni].z, bq[ni].w);
                mma_tf32(c[mi][ni], al[mi], bq[ni].x, bq[ni].y);
            }
    }
}

// GEMM1: x[t,j,ch] = mask * (cnn[lookup[order[j],t]] @ fc_w^T + fc_b)[ch]
__global__ void __launch_bounds__(128) k_gemm1(
    const float* __restrict__ cnn, const float* __restrict__ fcb,
    const int* __restrict__ lookup, float* __restrict__ xout) {
    __shared__ uint4 As[1024];
    __shared__ uint4 Bsm[1024];
    __shared__ int   simg[64];

    int j   = blockIdx.z;
    int t0  = blockIdx.y * 64;
    int m0  = blockIdx.x * 64;
    int tid = threadIdx.x;
    int len = g_lens[j];

    if (t0 >= len) {
        for (int i = tid; i < 1024; i += 128) {
            int r  = i >> 4;
            int cc = (i & 15) * 4;
            int t  = t0 + r;
            *(float4*)&xout[((size_t)t * BB + j) * DD + m0 + cc] =
                make_float4(0.f, 0.f, 0.f, 0.f);
        }
        return;
    }
    if (tid < 64) simg[tid] = lookup[g_order[j] * TT + t0 + tid];
    __syncthreads();

    int lane = tid & 31;
    int w    = tid >> 5;
    int wm   = w >> 1, wn = w & 1;
    int g    = lane >> 2, tg = lane & 3;
    int r    = tid >> 1, qp = tid & 1;
    size_t brow = (size_t)simg[r] * FEAT;

    float4 c[2][4];
#pragma unroll
    for (int mi = 0; mi < 2; mi++)
#pragma unroll
        for (int ni = 0; ni < 4; ni++) c[mi][ni] = make_float4(0.f,0.f,0.f,0.f);

    uint4  areg[8];
    float4 braw[4];
    {
        const uint4* at = g_wfc + ((size_t)blockIdx.x * 64 + 0) * 1024;
#pragma unroll
        for (int u = 0; u < 8; u++) areg[u] = at[tid + 128 * u];
        int kb = qp * 16;
#pragma unroll
        for (int u = 0; u < 4; u++)
            braw[u] = *(const float4*)&cnn[brow + kb + u * 4];
    }

    for (int kt = 0; kt < 64; kt++) {
        __syncthreads();
#pragma unroll
        for (int u = 0; u < 8; u++) As[tid + 128 * u] = areg[u];
        sts_b_convert(Bsm, braw, r, qp);
        __syncthreads();
        if (kt + 1 < 64) {
            const uint4* at = g_wfc + ((size_t)blockIdx.x * 64 + kt + 1) * 1024;
#pragma unroll
            for (int u = 0; u < 8; u++) areg[u] = at[tid + 128 * u];
            int kb = (kt + 1) * 32 + qp * 16;
#pragma unroll
            for (int u = 0; u < 4; u++)
                braw[u] = *(const float4*)&cnn[brow + kb + u * 4];
        }
        mma_ktile(As, Bsm, c, wm, wn, lane, g, tg);
    }

#pragma unroll
    for (int mi = 0; mi < 2; mi++) {
        int ch  = m0 + wm * 32 + mi * 16 + g;
        float b0 = fcb[ch], b8 = fcb[ch + 8];
#pragma unroll
        for (int ni = 0; ni < 4; ni++) {
            int tA = t0 + wn * 32 + ni * 8 + 2 * tg;
            bool v0 = (tA < len), v1 = (tA + 1 < len);
            size_t r0o = ((size_t)tA * BB + j) * DD;
            size_t r1o = ((size_t)(tA + 1) * BB + j) * DD;
            xout[r0o + ch]     = v0 ? c[mi][ni].x + b0 : 0.f;
            xout[r1o + ch]     = v1 ? c[mi][ni].y + b0 : 0.f;
            xout[r0o + ch + 8] = v0 ? c[mi][ni].z + b8 : 0.f;
            xout[r1o + ch + 8] = v1 ? c[mi][ni].w + b8 : 0.f;
        }
    }
}

// GEMM2: G[dir][j,t,ch] = x[t,j,:] @ w_ih[dir]^T
__global__ void __launch_bounds__(128) k_gemm2(const float* __restrict__ x) {
    __shared__ uint4 As[1024];
    __shared__ uint4 Bsm[1024];

    int dir = blockIdx.z;
    int j   = blockIdx.y >> 3;
    int t0  = (blockIdx.y & 7) * 64;
    int m0  = blockIdx.x * 64;
    int tid = threadIdx.x;
    int len = g_lens[j];
    if (t0 >= len) return;

    int lane = tid & 31;
    int w    = tid >> 5;
    int wm   = w >> 1, wn = w & 1;
    int g    = lane >> 2, tg = lane & 3;
    int r    = tid >> 1, qp = tid & 1;
    size_t brow = ((size_t)(t0 + r) * BB + j) * DD;

    float4 c[2][4];
#pragma unroll
    for (int mi = 0; mi < 2; mi++)
#pragma unroll
        for (int ni = 0; ni < 4; ni++) c[mi][ni] = make_float4(0.f,0.f,0.f,0.f);

    const uint4* wbase = g_wih[dir];
    uint4  areg[8];
    float4 braw[4];
    {
        const uint4* at = wbase + ((size_t)blockIdx.x * 16 + 0) * 1024;
#pragma unroll
        for (int u = 0; u < 8; u++) areg[u] = at[tid + 128 * u];
        int kb = qp * 16;
#pragma unroll
        for (int u = 0; u < 4; u++)
            braw[u] = *(const float4*)&x[brow + kb + u * 4];
    }

    for (int kt = 0; kt < 16; kt++) {
        __syncthreads();
#pragma unroll
        for (int u = 0; u < 8; u++) As[tid + 128 * u] = areg[u];
        sts_b_convert(Bsm, braw, r, qp);
        __syncthreads();
        if (kt + 1 < 16) {
            const uint4* at = wbase + ((size_t)blockIdx.x * 16 + kt + 1) * 1024;
#pragma unroll
            for (int u = 0; u < 8; u++) areg[u] = at[tid + 128 * u];
            int kb = (kt + 1) * 32 + qp * 16;
#pragma unroll
            for (int u = 0; u < 4; u++)
                braw[u] = *(const float4*)&x[brow + kb + u * 4];
        }
        mma_ktile(As, Bsm, c, wm, wn, lane, g, tg);
    }

    float* Gd = g_G + (size_t)dir * GSZ;
#pragma unroll
    for (int mi = 0; mi < 2; mi++) {
        int ch = m0 + wm * 32 + mi * 16 + g;
#pragma unroll
        for (int ni = 0; ni < 4; ni++) {
            int tA = t0 + wn * 32 + ni * 8 + 2 * tg;
            size_t r0o = ((size_t)j * TT + tA) * G4H;
            size_t r1o = ((size_t)j * TT + tA + 1) * G4H;
            Gd[r0o + ch]     = c[mi][ni].x;
            Gd[r1o + ch]     = c[mi][ni].y;
            Gd[r0o + ch + 8] = c[mi][ni].z;
            Gd[r1o + ch + 8] = c[mi][ni].w;
        }
    }
}

// ---------------- persistent scan kernel (v4: 512 thr, flag barrier) ----
// 128 CTAs (64/dir), 512 thr (16 warps). Dot role: warp w16 -> channel
// cl = w16>>1, gate pair gp = w16&1; lane: g = gp*2 + (lane>>4),
// ks = lane&15 (32-float K-slice). Pointwise role (tid<256): channel
// w16 = tid>>5, batch b = lane. R8 semantics: full staging, always-write
// pointwise (active ? hn : 0), always hbuf write, full TT loop.
__global__ void __launch_bounds__(512, 1) k_scan(
    const float* __restrict__ c0,
    const float* __restrict__ whhf, const float* __restrict__ whhb,
    const float* __restrict__ bihf, const float* __restrict__ bhhf,
    const float* __restrict__ bihb, const float* __restrict__ bhhb,
    float* __restrict__ out) {
    extern __shared__ float sm[];
    float* h_s    = sm;              // [32 b][576]: chunk c at c*36 + (k&31)
    float* g_s    = sm + GS_OFF;     // [32 b][36]: gate*8 + ch_local
    float* gate_s = sm + GATE_OFF;   // [8 cl][168]: b*5 + g

    int bid  = blockIdx.x;
    int dir  = bid >> 6;
    int ctad = bid & 63;
    int hcb  = ctad * 8;
    int tid  = threadIdx.x;
    int w16  = tid >> 5;
    int lane = tid & 31;
    // dot role
    int cl = w16 >> 1;
    int gp = w16 & 1;
    int g  = gp * 2 + (lane >> 4);
    int ks = lane & 15;
    int hc = hcb + cl;

    // --- W_hh slice into registers (32 floats = 8 f32x2-pairs) ---
    const float* whh = dir ? whhb : whhf;
    ulonglong2 warr[8];
    {
        const float* wrow = whh + (size_t)(g * HH + hc) * HH + ks * 32;
#pragma unroll
        for (int i = 0; i < 8; i++) {
            float4 v = *(const float4*)(wrow + i * 4);
            warr[i].x = packf2(v.x, v.y);
            warr[i].y = packf2(v.z, v.w);
        }
    }
    int lenw = g_lens[lane];        // lane <-> sorted batch

    // pointwise role state (tid < 256): channel pc = w16, batch = lane
    float bias[4];
    float creg = 0.f, hreg = 0.f;
    int   hc_pw = hcb + w16;        // valid for tid<256 (w16 = 0..7)
    if (tid < 256) {
        const float* bih = dir ? bihb : bihf;
        const float* bhh = dir ? bhhb : bhhf;
#pragma unroll
        for (int q = 0; q < 4; q++)
            bias[q] = bih[q * HH + hc_pw] + bhh[q * HH + hc_pw];
        creg = c0[dir * 16384 + lane * HH + hc_pw];
        hreg = g_hbuf[(dir * 2 + 0) * 16384 + lane * HH + hc_pw];
    }

    // G staging role (tid < 256)
    int sb  = tid >> 3;
    int sq  = tid & 7;
    int sg  = sq >> 1;
    int sh4 = (sq & 1) * 4;
    int slen = (tid < 256) ? g_lens[sb] : 0;
    const float* Gd = g_G + (size_t)dir * GSZ;
    size_t grow_base = ((size_t)sb * TT) * G4H + sg * HH + hcb + sh4;

    float4 ghold = make_float4(0.f, 0.f, 0.f, 0.f);
    if (tid < 256 && 0 < slen) {
        int tt0 = dir ? (slen - 1) : 0;
        ghold = *(const float4*)&Gd[grow_base + (size_t)tt0 * G4H];
    }

    volatile unsigned* myflag = &g_flags[dir][ctad];
    for (int s = 0; s < TT; s++) {
        int p = s & 1;
        unsigned actm = __ballot_sync(0xffffffffu, s < lenw);
        int nact = __popc(actm);

        // ---- stage full h (64KB) + G ----
        const float* hin = &g_hbuf[(dir * 2 + p) * 16384];
#pragma unroll
        for (int i = 0; i < 8; i++) {
            int idx = tid + 512 * i;             // float4 index
            float4 v = __ldcg((const float4*)&hin[idx * 4]);
            int b = idx >> 7;
            int k = (idx & 127) * 4;
            *(float4*)&h_s[b * PADH + (k >> 5) * 36 + (k & 31)] = v;
        }
        if (tid < 256)
            *(float4*)&g_s[sb * 36 + sg * 8 + sh4] = ghold;
        __syncthreads();

        // ---- dot phase over active batches (inactive results discarded) --
        const float* hbase = h_s + ks * 36;
#pragma unroll 2
        for (int b = 0; b < nact; b++) {
            const ulonglong2* hp = (const ulonglong2*)(hbase + b * PADH);
            unsigned long long a0 = 0, a1 = 0;
#pragma unroll
            for (int jj = 0; jj < 8; jj++) {
                ulonglong2 h2 = hp[jj];
                FMA2(a0, h2.x, warr[jj].x);
                FMA2(a1, h2.y, warr[jj].y);
            }
            float red = sum2(a0) + sum2(a1);
            red += __shfl_xor_sync(0xffffffffu, red, 1);
            red += __shfl_xor_sync(0xffffffffu, red, 2);
            red += __shfl_xor_sync(0xffffffffu, red, 4);
            red += __shfl_xor_sync(0xffffffffu, red, 8);
            if (ks == 0) gate_s[cl * 168 + b * 5 + g] = red;
        }
        __syncthreads();

        // ---- pointwise (tid < 256): R8 semantics ----
        if (tid < 256) {
            bool active = (s < lenw);
            float gi = gate_s[w16 * 168 + lane * 5 + 0] + g_s[lane * 36 + 0 * 8 + w16] + bias[0];
            float gf = gate_s[w16 * 168 + lane * 5 + 1] + g_s[lane * 36 + 1 * 8 + w16] + bias[1];
            float gg = gate_s[w16 * 168 + lane * 5 + 2] + g_s[lane * 36 + 2 * 8 + w16] + bias[2];
            float go = gate_s[w16 * 168 + lane * 5 + 3] + g_s[lane * 36 + 3 * 8 + w16] + bias[3];
            float i_ = 1.f / (1.f + __expf(-gi));
            float f_ = 1.f / (1.f + __expf(-gf));
            float g_ = tanhf(gg);
            float o_ = 1.f / (1.f + __expf(-go));
            float cn = f_ * creg + i_ * g_;
            float hn = o_ * tanhf(cn);

            if (dir == 0) {
                out[OUT_OFF + ((size_t)s * BB + lane) * 1024 + hc_pw] =
                    active ? hn : 0.f;
            } else {
                int tw = active ? (lenw - 1 - s) : s;
                out[OUT_OFF + ((size_t)tw * BB + lane) * 1024 + 512 + hc_pw] =
                    active ? hn : 0.f;
            }
            if (active) { creg = cn; hreg = hn; }
            g_hbuf[(dir * 2 + (1 - p)) * 16384 + lane * HH + hc_pw] = hreg;

            // prefetch G for next step (read-only, crosses the barrier)
            ghold = make_float4(0.f, 0.f, 0.f, 0.f);
            if (s + 1 < slen) {
                int tt = dir ? (slen - 2 - s) : (s + 1);
                ghold = *(const float4*)&Gd[grow_base + (size_t)tt * G4H];
            }
        }

        // ---- flag-array grid barrier (per direction) ----
        __syncthreads();
        if (tid == 0) {
            __threadfence();
            *myflag = (unsigned)(s + 1);
        }
        if (tid < 64) {
            volatile unsigned* fp = &g_flags[dir][tid];
            while (*fp < (unsigned)(s + 1)) { __nanosleep(40); }
            __threadfence();
        }
        __syncthreads();
    }
    if (tid < 256) {
        out[HN_OFF + dir * 16384 + lane * HH + hc_pw] = hreg;
        out[CN_OFF + dir * 16384 + lane * HH + hc_pw] = creg;
    }
}

// ---------------- launcher ----------------------------------------------
extern "C" void kernel_launch(void* const* d_in, const int* in_sizes, int n_in,
                              void* d_out, int out_size) {
    const float* cnn  = (const float*)d_in[0];
    const float* fcw  = (const float*)d_in[1];
    const float* fcb  = (const float*)d_in[2];
    const float* h0   = (const float*)d_in[3];
    const float* c0   = (const float*)d_in[4];
    const float* wihf = (const float*)d_in[5];
    const float* whhf = (const float*)d_in[6];
    const float* bihf = (const float*)d_in[7];
    const float* bhhf = (const float*)d_in[8];
    const float* wihb = (const float*)d_in[9];
    const float* whhb = (const float*)d_in[10];
    const float* bihb = (const float*)d_in[11];
    const float* bhhb = (const float*)d_in[12];
    const int* seq_lens = (const int*)d_in[13];
    const int* lookup   = (const int*)d_in[14];
    float* out = (float*)d_out;

    cudaFuncSetAttribute(k_scan, cudaFuncAttributeMaxDynamicSharedMemorySize,
                         SCAN_SMEM);

    k_reset<<<1, 256>>>(seq_lens, h0, out);
    k_prep<<<dim3(2048, 3), 256>>>(fcw, wihf, wihb);
    k_gemm1<<<dim3(8, 8, 32), 128>>>(cnn, fcb, lookup, out + X_OFF);
    k_gemm2<<<dim3(32, 256, 2), 128>>>(out + X_OFF);
    k_scan<<<128, 512, SCAN_SMEM>>>(c0, whhf, whhb, bihf, bhhf, bihb,
                                    bhhb, out);
}

// round 11
// speedup vs baseline: 1.2160x; 1.2160x over previous
#include <cuda_runtime.h>
#include <cstdint>

// Problem dims
#define TT    512
#define BB    32
#define DD    512
#define HH    512
#define FEAT  2048
#define G4H   2048   // 4*H

// Output layout (fp32, tuple order: out, h_n, c_n, x, lens_s)
#define OUT_OFF  0
#define HN_OFF   16777216
#define CN_OFF   (16777216 + 32768)
#define X_OFF    (16777216 + 65536)
#define LENS_OFF (X_OFF + 8388608)

#define GSZ       (512*32*2048)        // per-direction G size (floats)
#define WCHUNKS   524288               // frag chunks per weight matrix

// scan smem: h_s [32][544] (8 chunks of 64 @ stride 68), g_s [32][36],
// part [8 warps][32 b][36]
#define PADH      544
#define GS_OFF    (32*PADH)                 // 17408
#define PART_OFF  (GS_OFF + 32*36)          // 18560
#define SCAN_SMEM ((PART_OFF + 8*32*36) * 4)   // 111104 bytes

// ---------------- device scratch ---------------------------------------
__device__ float    g_G[2 * GSZ];          // input-gate preactivations (268MB)
__device__ float    g_hbuf[4 * 16384];     // [dir][pingpong][32][512]
__device__ int      g_order[BB];
__device__ int      g_lens[BB];
__device__ unsigned g_flags[2][64];        // per-dir per-CTA step flags
__device__ uint4    g_wfc[WCHUNKS];        // fc_w   frag-layout (hi/lo tf32)
__device__ uint4    g_wih[2][WCHUNKS];     // w_ih_f / w_ih_b frag-layout

// ---------------- helpers ----------------------------------------------
__device__ __forceinline__ uint32_t f2tf32(float v) {
    uint32_t r;
    asm("cvt.rna.tf32.f32 %0, %1;" : "=r"(r) : "f"(v));
    return r;
}

__device__ __forceinline__ void mma_tf32(float4& c, const uint4& a,
                                         uint32_t b0, uint32_t b1) {
    asm volatile(
        "mma.sync.aligned.m16n8k8.row.col.f32.tf32.tf32.f32 "
        "{%0,%1,%2,%3}, {%4,%5,%6,%7}, {%8,%9}, {%0,%1,%2,%3};"
        : "+f"(c.x), "+f"(c.y), "+f"(c.z), "+f"(c.w)
        : "r"(a.x), "r"(a.y), "r"(a.z), "r"(a.w), "r"(b0), "r"(b1));
}

#define FMA2(acc, a, b) \
    asm("fma.rn.f32x2 %0, %1, %2, %0;" : "+l"(acc) : "l"(a), "l"(b))

__device__ __forceinline__ float sum2(unsigned long long v) {
    float lo, hi;
    asm("mov.b64 {%0,%1}, %2;" : "=f"(lo), "=f"(hi) : "l"(v));
    return lo + hi;
}

__device__ __forceinline__ unsigned long long packf2(float a, float b) {
    unsigned long long u;
    asm("mov.b64 %0, {%1,%2};" : "=l"(u) : "f"(a), "f"(b));
    return u;
}

// ---------------- reset / sort kernel ----------------------------------
__global__ void k_reset(const int* __restrict__ seq_lens,
                        const float* __restrict__ h0,
                        float* __restrict__ out) {
    int tid = threadIdx.x;
    if (tid == 0) {
        unsigned used = 0u;
        for (int pos = 0; pos < BB; pos++) {
            int best = -1, bl = -1;
            for (int i = 0; i < BB; i++) {
                if (used & (1u << i)) continue;
                int L = seq_lens[i];
                if (L > bl) { bl = L; best = i; }
            }
            used |= 1u << best;
            g_order[pos] = best;
            g_lens[pos]  = bl;
            out[LENS_OFF + pos] = (float)bl;
        }
    }
    if (tid < 128) g_flags[tid >> 6][tid & 63] = 0u;
    for (int i = tid; i < 2 * 16384; i += blockDim.x) {
        int dir = i >> 14;
        int r   = i & 16383;
        g_hbuf[(dir * 2 + 0) * 16384 + r] = h0[i];
    }
}

// ---------------- weight pre-conversion to frag layout ------------------
__global__ void __launch_bounds__(256) k_prep(
    const float* __restrict__ fcw, const float* __restrict__ wihf,
    const float* __restrict__ wihb) {
    int z = blockIdx.y;
    const float* src = (z == 0) ? fcw : ((z == 1) ? wihf : wihb);
    uint4* dst = (z == 0) ? g_wfc : g_wih[z - 1];
    int K     = (z == 0) ? FEAT : DD;
    int nKtm1 = (z == 0) ? 63 : 15;
    int nKtsh = (z == 0) ? 6 : 4;

    int c    = blockIdx.x * 256 + threadIdx.x;
    int lane = c & 31;
    int hl   = (c >> 5) & 1;
    int s    = (c >> 6) & 3;
    int q    = (c >> 8) & 3;
    int tile = c >> 10;
    int qt   = tile & nKtm1;
    int r64  = tile >> nKtsh;
    int g    = lane >> 2, tg = lane & 3;
    int m0   = r64 * 64 + s * 16;
    int kk   = qt * 32 + q * 8 + tg;

    float v0 = src[(size_t)(m0 + g)     * K + kk];
    float v1 = src[(size_t)(m0 + g + 8) * K + kk];
    float v2 = src[(size_t)(m0 + g)     * K + kk + 4];
    float v3 = src[(size_t)(m0 + g + 8) * K + kk + 4];
    uint4 o;
    if (hl == 0) {
        o.x = f2tf32(v0); o.y = f2tf32(v1); o.z = f2tf32(v2); o.w = f2tf32(v3);
    } else {
        o.x = f2tf32(v0 - __uint_as_float(f2tf32(v0)));
        o.y = f2tf32(v1 - __uint_as_float(f2tf32(v1)));
        o.z = f2tf32(v2 - __uint_as_float(f2tf32(v2)));
        o.w = f2tf32(v3 - __uint_as_float(f2tf32(v3)));
    }
    dst[c] = o;
}

// ================= MMA GEMMs (A = weights frag-global, B = data rows) ==
__device__ __forceinline__ void sts_b_convert(uint4* Bsm, const float4* braw,
                                              int r, int qp) {
    int xr = (r & 3) ^ ((r >> 2) & 3);
#pragma unroll
    for (int oo = 0; oo < 2; oo++) {
        float f[8];
        f[0] = braw[oo*2].x;   f[1] = braw[oo*2].y;
        f[2] = braw[oo*2].z;   f[3] = braw[oo*2].w;
        f[4] = braw[oo*2+1].x; f[5] = braw[oo*2+1].y;
        f[6] = braw[oo*2+1].z; f[7] = braw[oo*2+1].w;
        uint32_t hi[8], lo[8];
#pragma unroll
        for (int p = 0; p < 8; p++) {
            hi[p] = f2tf32(f[p]);
            lo[p] = f2tf32(f[p] - __uint_as_float(hi[p]));
        }
        int q = qp * 2 + oo;
        int sbase = q * 256 + r * 4;
#pragma unroll
        for (int t2 = 0; t2 < 4; t2++) {
            uint4 ch;
            ch.x = hi[t2]; ch.y = hi[t2 + 4];
            ch.z = lo[t2]; ch.w = lo[t2 + 4];
            Bsm[sbase + (t2 ^ xr)] = ch;
        }
    }
}

__device__ __forceinline__ void mma_ktile(const uint4* As, const uint4* Bsm,
                                          float4 c[2][4], int wm, int wn,
                                          int lane, int g, int tg) {
#pragma unroll
    for (int q = 0; q < 4; q++) {
        uint4 ah[2], al[2], bq[4];
#pragma unroll
        for (int mi = 0; mi < 2; mi++) {
            int s = wm * 2 + mi;
            ah[mi] = As[((q * 4 + s) * 2 + 0) * 32 + lane];
            al[mi] = As[((q * 4 + s) * 2 + 1) * 32 + lane];
        }
#pragma unroll
        for (int ni = 0; ni < 4; ni++) {
            int rr = wn * 32 + ni * 8 + g;
            int sw = tg ^ (rr & 3) ^ ((rr >> 2) & 3);
            bq[ni] = Bsm[q * 256 + rr * 4 + sw];
        }
#pragma unroll
        for (int mi = 0; mi < 2; mi++)
#pragma unroll
            for (int ni = 0; ni < 4; ni++) {
                mma_tf32(c[mi][ni], ah[mi], bq[ni].x, bq[ni].y);
                mma_tf32(c[mi][ni], ah[mi], bq[ni].z, bq[ni].w);
                mma_tf32(c[mi][ni], al[mi], bq[ni].x, bq[ni].y);
            }
    }
}

// GEMM1: x[t,j,ch] = mask * (cnn[lookup[order[j],t]] @ fc_w^T + fc_b)[ch]
__global__ void __launch_bounds__(128) k_gemm1(
    const float* __restrict__ cnn, const float* __restrict__ fcb,
    const int* __restrict__ lookup, float* __restrict__ xout) {
    __shared__ uint4 As[1024];
    __shared__ uint4 Bsm[1024];
    __shared__ int   simg[64];

    int j   = blockIdx.z;
    int t0  = blockIdx.y * 64;
    int m0  = blockIdx.x * 64;
    int tid = threadIdx.x;
    int len = g_lens[j];

    if (t0 >= len) {
        for (int i = tid; i < 1024; i += 128) {
            int r  = i >> 4;
            int cc = (i & 15) * 4;
            int t  = t0 + r;
            *(float4*)&xout[((size_t)t * BB + j) * DD + m0 + cc] =
                make_float4(0.f, 0.f, 0.f, 0.f);
        }
        return;
    }
    if (tid < 64) simg[tid] = lookup[g_order[j] * TT + t0 + tid];
    __syncthreads();

    int lane = tid & 31;
    int w    = tid >> 5;
    int wm   = w >> 1, wn = w & 1;
    int g    = lane >> 2, tg = lane & 3;
    int r    = tid >> 1, qp = tid & 1;
    size_t brow = (size_t)simg[r] * FEAT;

    float4 c[2][4];
#pragma unroll
    for (int mi = 0; mi < 2; mi++)
#pragma unroll
        for (int ni = 0; ni < 4; ni++) c[mi][ni] = make_float4(0.f,0.f,0.f,0.f);

    uint4  areg[8];
    float4 braw[4];
    {
        const uint4* at = g_wfc + ((size_t)blockIdx.x * 64 + 0) * 1024;
#pragma unroll
        for (int u = 0; u < 8; u++) areg[u] = at[tid + 128 * u];
        int kb = qp * 16;
#pragma unroll
        for (int u = 0; u < 4; u++)
            braw[u] = *(const float4*)&cnn[brow + kb + u * 4];
    }

    for (int kt = 0; kt < 64; kt++) {
        __syncthreads();
#pragma unroll
        for (int u = 0; u < 8; u++) As[tid + 128 * u] = areg[u];
        sts_b_convert(Bsm, braw, r, qp);
        __syncthreads();
        if (kt + 1 < 64) {
            const uint4* at = g_wfc + ((size_t)blockIdx.x * 64 + kt + 1) * 1024;
#pragma unroll
            for (int u = 0; u < 8; u++) areg[u] = at[tid + 128 * u];
            int kb = (kt + 1) * 32 + qp * 16;
#pragma unroll
            for (int u = 0; u < 4; u++)
                braw[u] = *(const float4*)&cnn[brow + kb + u * 4];
        }
        mma_ktile(As, Bsm, c, wm, wn, lane, g, tg);
    }

#pragma unroll
    for (int mi = 0; mi < 2; mi++) {
        int ch  = m0 + wm * 32 + mi * 16 + g;
        float b0 = fcb[ch], b8 = fcb[ch + 8];
#pragma unroll
        for (int ni = 0; ni < 4; ni++) {
            int tA = t0 + wn * 32 + ni * 8 + 2 * tg;
            bool v0 = (tA < len), v1 = (tA + 1 < len);
            size_t r0o = ((size_t)tA * BB + j) * DD;
            size_t r1o = ((size_t)(tA + 1) * BB + j) * DD;
            xout[r0o + ch]     = v0 ? c[mi][ni].x + b0 : 0.f;
            xout[r1o + ch]     = v1 ? c[mi][ni].y + b0 : 0.f;
            xout[r0o + ch + 8] = v0 ? c[mi][ni].z + b8 : 0.f;
            xout[r1o + ch + 8] = v1 ? c[mi][ni].w + b8 : 0.f;
        }
    }
}

// GEMM2: G[dir][j,t,ch] = x[t,j,:] @ w_ih[dir]^T
__global__ void __launch_bounds__(128) k_gemm2(const float* __restrict__ x) {
    __shared__ uint4 As[1024];
    __shared__ uint4 Bsm[1024];

    int dir = blockIdx.z;
    int j   = blockIdx.y >> 3;
    int t0  = (blockIdx.y & 7) * 64;
    int m0  = blockIdx.x * 64;
    int tid = threadIdx.x;
    int len = g_lens[j];
    if (t0 >= len) return;

    int lane = tid & 31;
    int w    = tid >> 5;
    int wm   = w >> 1, wn = w & 1;
    int g    = lane >> 2, tg = lane & 3;
    int r    = tid >> 1, qp = tid & 1;
    size_t brow = ((size_t)(t0 + r) * BB + j) * DD;

    float4 c[2][4];
#pragma unroll
    for (int mi = 0; mi < 2; mi++)
#pragma unroll
        for (int ni = 0; ni < 4; ni++) c[mi][ni] = make_float4(0.f,0.f,0.f,0.f);

    const uint4* wbase = g_wih[dir];
    uint4  areg[8];
    float4 braw[4];
    {
        const uint4* at = wbase + ((size_t)blockIdx.x * 16 + 0) * 1024;
#pragma unroll
        for (int u = 0; u < 8; u++) areg[u] = at[tid + 128 * u];
        int kb = qp * 16;
#pragma unroll
        for (int u = 0; u < 4; u++)
            braw[u] = *(const float4*)&x[brow + kb + u * 4];
    }

    for (int kt = 0; kt < 16; kt++) {
        __syncthreads();
#pragma unroll
        for (int u = 0; u < 8; u++) As[tid + 128 * u] = areg[u];
        sts_b_convert(Bsm, braw, r, qp);
        __syncthreads();
        if (kt + 1 < 16) {
            const uint4* at = wbase + ((size_t)blockIdx.x * 16 + kt + 1) * 1024;
#pragma unroll
            for (int u = 0; u < 8; u++) areg[u] = at[tid + 128 * u];
            int kb = (kt + 1) * 32 + qp * 16;
#pragma unroll
            for (int u = 0; u < 4; u++)
                braw[u] = *(const float4*)&x[brow + kb + u * 4];
        }
        mma_ktile(As, Bsm, c, wm, wn, lane, g, tg);
    }

    float* Gd = g_G + (size_t)dir * GSZ;
#pragma unroll
    for (int mi = 0; mi < 2; mi++) {
        int ch = m0 + wm * 32 + mi * 16 + g;
#pragma unroll
        for (int ni = 0; ni < 4; ni++) {
            int tA = t0 + wn * 32 + ni * 8 + 2 * tg;
            size_t r0o = ((size_t)j * TT + tA) * G4H;
            size_t r1o = ((size_t)j * TT + tA + 1) * G4H;
            Gd[r0o + ch]     = c[mi][ni].x;
            Gd[r1o + ch]     = c[mi][ni].y;
            Gd[r0o + ch + 8] = c[mi][ni].z;
            Gd[r1o + ch + 8] = c[mi][ni].w;
        }
    }
}

// ---------------- persistent scan kernel (v5: W regs + STS reduce) ------
// 128 CTAs (64/dir), 256 thr (8 warps). Warp w -> hc = ctad*8 + w.
// Dot lane: g = lane&3 (gate), ks = lane>>2 (64-float K-slice) [v2 layout].
// Reduction via STS partials (part[w][b*36+lane]) gathered by pointwise
// thread (w, lane=b) as 8x LDS.128 — no shuffles. R8/R10 semantics:
// full staging, always-write pointwise, full TT loop, nact dot trunc.
__global__ void __launch_bounds__(256, 1) k_scan(
    const float* __restrict__ c0,
    const float* __restrict__ whhf, const float* __restrict__ whhb,
    const float* __restrict__ bihf, const float* __restrict__ bhhf,
    const float* __restrict__ bihb, const float* __restrict__ bhhb,
    float* __restrict__ out) {
    extern __shared__ float sm[];
    float* h_s  = sm;                 // [32 b][544]: chunk c at c*68 + (k&63)
    float* g_s  = sm + GS_OFF;        // [32 b][36]: gate*8 + ch_local
    float* part = sm + PART_OFF;      // [8 w][32 b][36]: + lane

    int bid  = blockIdx.x;
    int dir  = bid >> 6;
    int ctad = bid & 63;
    int hcb  = ctad * 8;
    int tid  = threadIdx.x;
    int w    = tid >> 5;
    int lane = tid & 31;
    int g    = lane & 3;
    int ks   = lane >> 2;
    int hc   = hcb + w;

    // --- W_hh slice into registers (64 floats = 16 f32x2-pairs) [v2] ---
    const float* whh = dir ? whhb : whhf;
    ulonglong2 warr[16];
    {
        const float* wrow = whh + (size_t)(g * HH + hc) * HH + ks * 64;
#pragma unroll
        for (int i = 0; i < 16; i++) {
            float4 v = *(const float4*)(wrow + i * 4);
            warr[i].x = packf2(v.x, v.y);
            warr[i].y = packf2(v.z, v.w);
        }
    }
    float bias[4];
    {
        const float* bih = dir ? bihb : bihf;
        const float* bhh = dir ? bhhb : bhhf;
#pragma unroll
        for (int q = 0; q < 4; q++)
            bias[q] = bih[q * HH + hc] + bhh[q * HH + hc];
    }
    int   lenb = g_lens[lane];
    float creg = c0[dir * 16384 + lane * HH + hc];
    float hreg = g_hbuf[(dir * 2 + 0) * 16384 + lane * HH + hc];

    // G staging role
    int sb  = tid >> 3;
    int sq  = tid & 7;
    int sg  = sq >> 1;
    int sh4 = (sq & 1) * 4;
    int slen = g_lens[sb];
    const float* Gd = g_G + (size_t)dir * GSZ;
    size_t grow_base = ((size_t)sb * TT) * G4H + sg * HH + hcb + sh4;

    float4 ghold = make_float4(0.f, 0.f, 0.f, 0.f);
    if (0 < slen) {
        int tt0 = dir ? (slen - 1) : 0;
        ghold = *(const float4*)&Gd[grow_base + (size_t)tt0 * G4H];
    }

    volatile unsigned* myflag = &g_flags[dir][ctad];
    float* pwsts = part + w * 1152 + lane;   // STS target base

    for (int s = 0; s < TT; s++) {
        int p = s & 1;
        unsigned actm = __ballot_sync(0xffffffffu, s < lenb);
        int nact = __popc(actm);

        // ---- stage full h (64KB) + G (R8-proven full staging) ----
        const float* hin = &g_hbuf[(dir * 2 + p) * 16384];
#pragma unroll 4
        for (int i = 0; i < 16; i++) {
            int idx = tid + 256 * i;             // float4 index
            float4 v = __ldcg((const float4*)&hin[idx * 4]);
            int b = idx >> 7;
            int k = (idx & 127) * 4;
            *(float4*)&h_s[b * PADH + (k >> 6) * 68 + (k & 63)] = v;
        }
        *(float4*)&g_s[sb * 36 + sg * 8 + sh4] = ghold;
        __syncthreads();

        // ---- dot phase: per b, 64-MAC slice -> STS partial ----
        const float* hbase = h_s + ks * 68;
#pragma unroll 2
        for (int b = 0; b < nact; b++) {
            const ulonglong2* hp = (const ulonglong2*)(hbase + b * PADH);
            unsigned long long a0 = 0, a1 = 0;
#pragma unroll
            for (int jj = 0; jj < 16; jj++) {
                ulonglong2 h2 = hp[jj];
                FMA2(a0, h2.x, warr[jj].x);
                FMA2(a1, h2.y, warr[jj].y);
            }
            pwsts[b * 36] = sum2(a0) + sum2(a1);   // 1 wf STS.32
        }
        __syncwarp();

        // ---- pointwise: thread (w, lane=b); gather 8x LDS.128 ----
        {
            bool active = (s < lenb);
            const float4* pp = (const float4*)(part + w * 1152 + lane * 36);
            float4 s4 = pp[0];
#pragma unroll
            for (int jq = 1; jq < 8; jq++) {
                float4 t = pp[jq];
                s4.x += t.x; s4.y += t.y; s4.z += t.z; s4.w += t.w;
            }
            float gi = s4.x + g_s[lane * 36 + 0 * 8 + w] + bias[0];
            float gf = s4.y + g_s[lane * 36 + 1 * 8 + w] + bias[1];
            float gg = s4.z + g_s[lane * 36 + 2 * 8 + w] + bias[2];
            float go = s4.w + g_s[lane * 36 + 3 * 8 + w] + bias[3];
            float i_ = 1.f / (1.f + __expf(-gi));
            float f_ = 1.f / (1.f + __expf(-gf));
            float g_ = tanhf(gg);
            float o_ = 1.f / (1.f + __expf(-go));
            float cn = f_ * creg + i_ * g_;
            float hn = o_ * tanhf(cn);

            if (dir == 0) {
                out[OUT_OFF + ((size_t)s * BB + lane) * 1024 + hc] =
                    active ? hn : 0.f;
            } else {
                int tw = active ? (lenb - 1 - s) : s;
                out[OUT_OFF + ((size_t)tw * BB + lane) * 1024 + 512 + hc] =
                    active ? hn : 0.f;
            }
            if (active) { creg = cn; hreg = hn; }
            g_hbuf[(dir * 2 + (1 - p)) * 16384 + lane * HH + hc] = hreg;
        }

        // ---- prefetch G for next step (read-only, crosses barrier) ----
        ghold = make_float4(0.f, 0.f, 0.f, 0.f);
        if (s + 1 < slen) {
            int tt = dir ? (slen - 2 - s) : (s + 1);
            ghold = *(const float4*)&Gd[grow_base + (size_t)tt * G4H];
        }

        // ---- flag-array grid barrier (per direction, R10-proven) ----
        __syncthreads();
        if (tid == 0) {
            __threadfence();
            *myflag = (unsigned)(s + 1);
        }
        if (tid < 64) {
            volatile unsigned* fp = &g_flags[dir][tid];
            while (*fp < (unsigned)(s + 1)) { __nanosleep(20); }
            __threadfence();
        }
        __syncthreads();
    }
    out[HN_OFF + dir * 16384 + lane * HH + hc] = hreg;
    out[CN_OFF + dir * 16384 + lane * HH + hc] = creg;
}

// ---------------- launcher ----------------------------------------------
extern "C" void kernel_launch(void* const* d_in, const int* in_sizes, int n_in,
                              void* d_out, int out_size) {
    const float* cnn  = (const float*)d_in[0];
    const float* fcw  = (const float*)d_in[1];
    const float* fcb  = (const float*)d_in[2];
    const float* h0   = (const float*)d_in[3];
    const float* c0   = (const float*)d_in[4];
    const float* wihf = (const float*)d_in[5];
    const float* whhf = (const float*)d_in[6];
    const float* bihf = (const float*)d_in[7];
    const float* bhhf = (const float*)d_in[8];
    const float* wihb = (const float*)d_in[9];
    const float* whhb = (const float*)d_in[10];
    const float* bihb = (const float*)d_in[11];
    const float* bhhb = (const float*)d_in[12];
    const int* seq_lens = (const int*)d_in[13];
    const int* lookup   = (const int*)d_in[14];
    float* out = (float*)d_out;

    cudaFuncSetAttribute(k_scan, cudaFuncAttributeMaxDynamicSharedMemorySize,
                         SCAN_SMEM);

    k_reset<<<1, 256>>>(seq_lens, h0, out);
    k_prep<<<dim3(2048, 3), 256>>>(fcw, wihf, wihb);
    k_gemm1<<<dim3(8, 8, 32), 128>>>(cnn, fcb, lookup, out + X_OFF);
    k_gemm2<<<dim3(32, 256, 2), 128>>>(out + X_OFF);
    k_scan<<<128, 256, SCAN_SMEM>>>(c0, whhf, whhb, bihf, bhhf, bihb,
                                    bhhb, out);
}

// round 12
// speedup vs baseline: 1.3921x; 1.1449x over previous
#include <cuda_runtime.h>
#include <cstdint>

// Problem dims
#define TT    512
#define BB    32
#define DD    512
#define HH    512
#define FEAT  2048
#define G4H   2048   // 4*H

// Output layout (fp32, tuple order: out, h_n, c_n, x, lens_s)
#define OUT_OFF  0
#define HN_OFF   16777216
#define CN_OFF   (16777216 + 32768)
#define X_OFF    (16777216 + 65536)
#define LENS_OFF (X_OFF + 8388608)

#define GSZ       (512*32*2048)        // per-direction G size (floats)
#define WCHUNKS   524288               // frag chunks per weight matrix

// ---------------- device scratch ---------------------------------------
__device__ float    g_G[2 * GSZ];          // input-gate preactivations (268MB)
__device__ float    g_hring[2][4][BB][HH]; // h ring buffer, depth 4
__device__ unsigned g_done[2][TT][4];      // per (dir, step, group) counters
__device__ int      g_order[BB];
__device__ int      g_lens[BB];
__device__ uint4    g_wfc[WCHUNKS];        // fc_w   frag-layout (hi/lo tf32)
__device__ uint4    g_wih[2][WCHUNKS];     // w_ih_f / w_ih_b frag-layout

// ---------------- helpers ----------------------------------------------
__device__ __forceinline__ uint32_t f2tf32(float v) {
    uint32_t r;
    asm("cvt.rna.tf32.f32 %0, %1;" : "=r"(r) : "f"(v));
    return r;
}

__device__ __forceinline__ void mma_tf32(float4& c, const uint4& a,
                                         uint32_t b0, uint32_t b1) {
    asm volatile(
        "mma.sync.aligned.m16n8k8.row.col.f32.tf32.tf32.f32 "
        "{%0,%1,%2,%3}, {%4,%5,%6,%7}, {%8,%9}, {%0,%1,%2,%3};"
        : "+f"(c.x), "+f"(c.y), "+f"(c.z), "+f"(c.w)
        : "r"(a.x), "r"(a.y), "r"(a.z), "r"(a.w), "r"(b0), "r"(b1));
}

#define FMA2(acc, a, b) \
    asm("fma.rn.f32x2 %0, %1, %2, %0;" : "+l"(acc) : "l"(a), "l"(b))

__device__ __forceinline__ float sum2(unsigned long long v) {
    float lo, hi;
    asm("mov.b64 {%0,%1}, %2;" : "=f"(lo), "=f"(hi) : "l"(v));
    return lo + hi;
}

__device__ __forceinline__ unsigned long long packf2(float a, float b) {
    unsigned long long u;
    asm("mov.b64 %0, {%1,%2};" : "=l"(u) : "f"(a), "f"(b));
    return u;
}

// ---------------- reset / sort kernel ----------------------------------
__global__ void k_reset(const int* __restrict__ seq_lens,
                        const float* __restrict__ h0,
                        float* __restrict__ out) {
    int tid = threadIdx.x;
    if (tid == 0) {
        unsigned used = 0u;
        for (int pos = 0; pos < BB; pos++) {
            int best = -1, bl = -1;
            for (int i = 0; i < BB; i++) {
                if (used & (1u << i)) continue;
                int L = seq_lens[i];
                if (L > bl) { bl = L; best = i; }
            }
            used |= 1u << best;
            g_order[pos] = best;
            g_lens[pos]  = bl;
            out[LENS_OFF + pos] = (float)bl;
        }
    }
    // zero done counters
    for (int i = tid; i < 2 * TT * 4; i += blockDim.x)
        ((unsigned*)g_done)[i] = 0u;
    // ring slot 0 <- h0
    for (int i = tid; i < 2 * 16384; i += blockDim.x) {
        int dir = i >> 14;
        int r   = i & 16383;
        g_hring[dir][0][r >> 9][r & 511] = h0[i];
    }
}

// ---------------- bulk zero of the `out` region -------------------------
__global__ void __launch_bounds__(256) k_zero(float* __restrict__ out) {
    size_t i = ((size_t)blockIdx.x * 256 + threadIdx.x) * 4;
    *(float4*)&out[OUT_OFF + i] = make_float4(0.f, 0.f, 0.f, 0.f);
}

// ---------------- weight pre-conversion to frag layout ------------------
__global__ void __launch_bounds__(256) k_prep(
    const float* __restrict__ fcw, const float* __restrict__ wihf,
    const float* __restrict__ wihb) {
    int z = blockIdx.y;
    const float* src = (z == 0) ? fcw : ((z == 1) ? wihf : wihb);
    uint4* dst = (z == 0) ? g_wfc : g_wih[z - 1];
    int K     = (z == 0) ? FEAT : DD;
    int nKtm1 = (z == 0) ? 63 : 15;
    int nKtsh = (z == 0) ? 6 : 4;

    int c    = blockIdx.x * 256 + threadIdx.x;
    int lane = c & 31;
    int hl   = (c >> 5) & 1;
    int s    = (c >> 6) & 3;
    int q    = (c >> 8) & 3;
    int tile = c >> 10;
    int qt   = tile & nKtm1;
    int r64  = tile >> nKtsh;
    int g    = lane >> 2, tg = lane & 3;
    int m0   = r64 * 64 + s * 16;
    int kk   = qt * 32 + q * 8 + tg;

    float v0 = src[(size_t)(m0 + g)     * K + kk];
    float v1 = src[(size_t)(m0 + g + 8) * K + kk];
    float v2 = src[(size_t)(m0 + g)     * K + kk + 4];
    float v3 = src[(size_t)(m0 + g + 8) * K + kk + 4];
    uint4 o;
    if (hl == 0) {
        o.x = f2tf32(v0); o.y = f2tf32(v1); o.z = f2tf32(v2); o.w = f2tf32(v3);
    } else {
        o.x = f2tf32(v0 - __uint_as_float(f2tf32(v0)));
        o.y = f2tf32(v1 - __uint_as_float(f2tf32(v1)));
        o.z = f2tf32(v2 - __uint_as_float(f2tf32(v2)));
        o.w = f2tf32(v3 - __uint_as_float(f2tf32(v3)));
    }
    dst[c] = o;
}

// ================= MMA GEMMs (A = weights frag-global, B = data rows) ==
__device__ __forceinline__ void sts_b_convert(uint4* Bsm, const float4* braw,
                                              int r, int qp) {
    int xr = (r & 3) ^ ((r >> 2) & 3);
#pragma unroll
    for (int oo = 0; oo < 2; oo++) {
        float f[8];
        f[0] = braw[oo*2].x;   f[1] = braw[oo*2].y;
        f[2] = braw[oo*2].z;   f[3] = braw[oo*2].w;
        f[4] = braw[oo*2+1].x; f[5] = braw[oo*2+1].y;
        f[6] = braw[oo*2+1].z; f[7] = braw[oo*2+1].w;
        uint32_t hi[8], lo[8];
#pragma unroll
        for (int p = 0; p < 8; p++) {
            hi[p] = f2tf32(f[p]);
            lo[p] = f2tf32(f[p] - __uint_as_float(hi[p]));
        }
        int q = qp * 2 + oo;
        int sbase = q * 256 + r * 4;
#pragma unroll
        for (int t2 = 0; t2 < 4; t2++) {
            uint4 ch;
            ch.x = hi[t2]; ch.y = hi[t2 + 4];
            ch.z = lo[t2]; ch.w = lo[t2 + 4];
            Bsm[sbase + (t2 ^ xr)] = ch;
        }
    }
}

__device__ __forceinline__ void mma_ktile(const uint4* As, const uint4* Bsm,
                                          float4 c[2][4], int wm, int wn,
                                          int lane, int g, int tg) {
#pragma unroll
    for (int q = 0; q < 4; q++) {
        uint4 ah[2], al[2], bq[4];
#pragma unroll
        for (int mi = 0; mi < 2; mi++) {
            int s = wm * 2 + mi;
            ah[mi] = As[((q * 4 + s) * 2 + 0) * 32 + lane];
            al[mi] = As[((q * 4 + s) * 2 + 1) * 32 + lane];
        }
#pragma unroll
        for (int ni = 0; ni < 4; ni++) {
            int rr = wn * 32 + ni * 8 + g;
            int sw = tg ^ (rr & 3) ^ ((rr >> 2) & 3);
            bq[ni] = Bsm[q * 256 + rr * 4 + sw];
        }
#pragma unroll
        for (int mi = 0; mi < 2; mi++)
#pragma unroll
            for (int ni = 0; ni < 4; ni++) {
                mma_tf32(c[mi][ni], ah[mi], bq[ni].x, bq[ni].y);
                mma_tf32(c[mi][ni], ah[mi], bq[ni].z, bq[ni].w);
                mma_tf32(c[mi][ni], al[mi], bq[ni].x, bq[ni].y);
            }
    }
}

// GEMM1: x[t,j,ch] = mask * (cnn[lookup[order[j],t]] @ fc_w^T + fc_b)[ch]
__global__ void __launch_bounds__(128) k_gemm1(
    const float* __restrict__ cnn, const float* __restrict__ fcb,
    const int* __restrict__ lookup, float* __restrict__ xout) {
    __shared__ uint4 As[1024];
    __shared__ uint4 Bsm[1024];
    __shared__ int   simg[64];

    int j   = blockIdx.z;
    int t0  = blockIdx.y * 64;
    int m0  = blockIdx.x * 64;
    int tid = threadIdx.x;
    int len = g_lens[j];

    if (t0 >= len) {
        for (int i = tid; i < 1024; i += 128) {
            int r  = i >> 4;
            int cc = (i & 15) * 4;
            int t  = t0 + r;
            *(float4*)&xout[((size_t)t * BB + j) * DD + m0 + cc] =
                make_float4(0.f, 0.f, 0.f, 0.f);
        }
        return;
    }
    if (tid < 64) simg[tid] = lookup[g_order[j] * TT + t0 + tid];
    __syncthreads();

    int lane = tid & 31;
    int w    = tid >> 5;
    int wm   = w >> 1, wn = w & 1;
    int g    = lane >> 2, tg = lane & 3;
    int r    = tid >> 1, qp = tid & 1;
    size_t brow = (size_t)simg[r] * FEAT;

    float4 c[2][4];
#pragma unroll
    for (int mi = 0; mi < 2; mi++)
#pragma unroll
        for (int ni = 0; ni < 4; ni++) c[mi][ni] = make_float4(0.f,0.f,0.f,0.f);

    uint4  areg[8];
    float4 braw[4];
    {
        const uint4* at = g_wfc + ((size_t)blockIdx.x * 64 + 0) * 1024;
#pragma unroll
        for (int u = 0; u < 8; u++) areg[u] = at[tid + 128 * u];
        int kb = qp * 16;
#pragma unroll
        for (int u = 0; u < 4; u++)
            braw[u] = *(const float4*)&cnn[brow + kb + u * 4];
    }

    for (int kt = 0; kt < 64; kt++) {
        __syncthreads();
#pragma unroll
        for (int u = 0; u < 8; u++) As[tid + 128 * u] = areg[u];
        sts_b_convert(Bsm, braw, r, qp);
        __syncthreads();
        if (kt + 1 < 64) {
            const uint4* at = g_wfc + ((size_t)blockIdx.x * 64 + kt + 1) * 1024;
#pragma unroll
            for (int u = 0; u < 8; u++) areg[u] = at[tid + 128 * u];
            int kb = (kt + 1) * 32 + qp * 16;
#pragma unroll
            for (int u = 0; u < 4; u++)
                braw[u] = *(const float4*)&cnn[brow + kb + u * 4];
        }
        mma_ktile(As, Bsm, c, wm, wn, lane, g, tg);
    }

#pragma unroll
    for (int mi = 0; mi < 2; mi++) {
        int ch  = m0 + wm * 32 + mi * 16 + g;
        float b0 = fcb[ch], b8 = fcb[ch + 8];
#pragma unroll
        for (int ni = 0; ni < 4; ni++) {
            int tA = t0 + wn * 32 + ni * 8 + 2 * tg;
            bool v0 = (tA < len), v1 = (tA + 1 < len);
            size_t r0o = ((size_t)tA * BB + j) * DD;
            size_t r1o = ((size_t)(tA + 1) * BB + j) * DD;
            xout[r0o + ch]     = v0 ? c[mi][ni].x + b0 : 0.f;
            xout[r1o + ch]     = v1 ? c[mi][ni].y + b0 : 0.f;
            xout[r0o + ch + 8] = v0 ? c[mi][ni].z + b8 : 0.f;
            xout[r1o + ch + 8] = v1 ? c[mi][ni].w + b8 : 0.f;
        }
    }
}

// GEMM2: G[dir][j,t,ch] = x[t,j,:] @ w_ih[dir]^T
__global__ void __launch_bounds__(128) k_gemm2(const float* __restrict__ x) {
    __shared__ uint4 As[1024];
    __shared__ uint4 Bsm[1024];

    int dir = blockIdx.z;
    int j   = blockIdx.y >> 3;
    int t0  = (blockIdx.y & 7) * 64;
    int m0  = blockIdx.x * 64;
    int tid = threadIdx.x;
    int len = g_lens[j];
    if (t0 >= len) return;

    int lane = tid & 31;
    int w    = tid >> 5;
    int wm   = w >> 1, wn = w & 1;
    int g    = lane >> 2, tg = lane & 3;
    int r    = tid >> 1, qp = tid & 1;
    size_t brow = ((size_t)(t0 + r) * BB + j) * DD;

    float4 c[2][4];
#pragma unroll
    for (int mi = 0; mi < 2; mi++)
#pragma unroll
        for (int ni = 0; ni < 4; ni++) c[mi][ni] = make_float4(0.f,0.f,0.f,0.f);

    const uint4* wbase = g_wih[dir];
    uint4  areg[8];
    float4 braw[4];
    {
        const uint4* at = wbase + ((size_t)blockIdx.x * 16 + 0) * 1024;
#pragma unroll
        for (int u = 0; u < 8; u++) areg[u] = at[tid + 128 * u];
        int kb = qp * 16;
#pragma unroll
        for (int u = 0; u < 4; u++)
            braw[u] = *(const float4*)&x[brow + kb + u * 4];
    }

    for (int kt = 0; kt < 16; kt++) {
        __syncthreads();
#pragma unroll
        for (int u = 0; u < 8; u++) As[tid + 128 * u] = areg[u];
        sts_b_convert(Bsm, braw, r, qp);
        __syncthreads();
        if (kt + 1 < 16) {
            const uint4* at = wbase + ((size_t)blockIdx.x * 16 + kt + 1) * 1024;
#pragma unroll
            for (int u = 0; u < 8; u++) areg[u] = at[tid + 128 * u];
            int kb = (kt + 1) * 32 + qp * 16;
#pragma unroll
            for (int u = 0; u < 4; u++)
                braw[u] = *(const float4*)&x[brow + kb + u * 4];
        }
        mma_ktile(As, Bsm, c, wm, wn, lane, g, tg);
    }

    float* Gd = g_G + (size_t)dir * GSZ;
#pragma unroll
    for (int mi = 0; mi < 2; mi++) {
        int ch = m0 + wm * 32 + mi * 16 + g;
#pragma unroll
        for (int ni = 0; ni < 4; ni++) {
            int tA = t0 + wn * 32 + ni * 8 + 2 * tg;
            size_t r0o = ((size_t)j * TT + tA) * G4H;
            size_t r1o = ((size_t)j * TT + tA + 1) * G4H;
            Gd[r0o + ch]     = c[mi][ni].x;
            Gd[r1o + ch]     = c[mi][ni].y;
            Gd[r0o + ch + 8] = c[mi][ni].z;
            Gd[r1o + ch + 8] = c[mi][ni].w;
        }
    }
}

// ---------------- persistent scan kernel (v6: batch-pipelined, NO grid
// barrier). 128 CTAs (64/dir), 256 thr. CTA owns 8 channels. Ticks (s,g)
// over groups of 8 batches; per-(s,g) done counters; h through a depth-4
// global ring. Dot: v5-proven W-in-regs + STS-partial reduce.
__global__ void __launch_bounds__(256, 1) k_scan(
    const float* __restrict__ c0, const float* __restrict__ h0,
    const float* __restrict__ whhf, const float* __restrict__ whhb,
    const float* __restrict__ bihf, const float* __restrict__ bhhf,
    const float* __restrict__ bihb, const float* __restrict__ bhhb,
    float* __restrict__ out) {
    __shared__ float h_s[8 * 544];     // 8 rows, chunk c at c*68 + (k&63)
    __shared__ float g_sm[8 * 36];     // [b_local][gate*8 + ch_local]
    __shared__ float part[8 * 288];    // [warp][b_local*36 + lane]

    int bid  = blockIdx.x;
    int dir  = bid >> 6;
    int ctad = bid & 63;
    int hcb  = ctad * 8;
    int tid  = threadIdx.x;
    int w    = tid >> 5;
    int lane = tid & 31;
    int g4   = lane & 3;                // gate (dot role)
    int ks   = lane >> 2;               // 64-float K-slice (dot role)
    int hc   = hcb + w;

    // --- W_hh slice into registers (v5-proven) ---
    const float* whh = dir ? whhb : whhf;
    ulonglong2 warr[16];
    {
        const float* wrow = whh + (size_t)(g4 * HH + hc) * HH + ks * 64;
#pragma unroll
        for (int i = 0; i < 16; i++) {
            float4 v = *(const float4*)(wrow + i * 4);
            warr[i].x = packf2(v.x, v.y);
            warr[i].y = packf2(v.z, v.w);
        }
    }
    float bias[4];
    {
        const float* bih = dir ? bihb : bihf;
        const float* bhh = dir ? bhhb : bhhf;
#pragma unroll
        for (int q = 0; q < 4; q++)
            bias[q] = bih[q * HH + hc] + bhh[q * HH + hc];
    }

    // pointwise state: thread (w, lane<8) owns batches {g*8+lane}
    float creg[4], hreg[4];
    int   lenp[4];
    if (lane < 8) {
#pragma unroll
        for (int g = 0; g < 4; g++) {
            int b = g * 8 + lane;
            lenp[g] = g_lens[b];
            creg[g] = c0[dir * 16384 + b * HH + hc];
            hreg[g] = h0[dir * 16384 + b * HH + hc];
        }
    }

    // G loader role: thread -> (b_local, gate, ch)
    int lb  = tid >> 5;                 // b_local 0..7
    int lg  = (tid & 31) >> 3;          // gate 0..3
    int lch = tid & 7;                  // ch_local 0..7
    const float* Gd = g_G + (size_t)dir * GSZ;

    int glen[4];
#pragma unroll
    for (int g = 0; g < 4; g++) glen[g] = g_lens[g * 8];
    int maxlen = glen[0];

    for (int s = 0; s < maxlen; s++) {
        int rd = s & 3, wr = (s + 1) & 3;
#pragma unroll 1
        for (int g = 0; g < 4; g++) {
            if (s >= glen[g]) continue;

            // G load for this tick (1 float/thread), overlaps the poll
            int   bG   = g * 8 + lb;
            int   lenG = g_lens[bG];
            float gval = 0.f;
            if (s < lenG) {
                int tt = dir ? (lenG - 1 - s) : s;
                gval = __ldg(&Gd[((size_t)bG * TT + tt) * G4H +
                                 lg * HH + hcb + lch]);
            }

            // wait for h(s)[group g] from all 64 CTAs of this dir
            if (s > 0) {
                if (tid == 0) {
                    volatile unsigned* fp = &g_done[dir][s - 1][g];
                    while (*fp < 64u) __nanosleep(20);
                }
                __syncthreads();
            }

            // stage 8 h rows (16KB) via L2 + G into smem
            const float* hin = &g_hring[dir][rd][g * 8][0];
#pragma unroll
            for (int i = 0; i < 4; i++) {
                int idx = tid + 256 * i;        // float4 index, 1024 total
                float4 v = __ldcg((const float4*)&hin[idx * 4]);
                int b = idx >> 7;
                int k = (idx & 127) * 4;
                *(float4*)&h_s[b * 544 + (k >> 6) * 68 + (k & 63)] = v;
            }
            g_sm[lb * 36 + lg * 8 + lch] = gval;
            __syncthreads();

            // dot: per b_local, 64-MAC slice -> STS partial
            const float* hbase = h_s + ks * 68;
            float* psts = part + w * 288 + lane;
#pragma unroll 2
            for (int b = 0; b < 8; b++) {
                const ulonglong2* hp = (const ulonglong2*)(hbase + b * 544);
                unsigned long long a0 = 0, a1 = 0;
#pragma unroll
                for (int jj = 0; jj < 16; jj++) {
                    ulonglong2 h2 = hp[jj];
                    FMA2(a0, h2.x, warr[jj].x);
                    FMA2(a1, h2.y, warr[jj].y);
                }
                psts[b * 36] = sum2(a0) + sum2(a1);
            }
            __syncwarp();

            // pointwise: thread (w, lane<8) for batch b = g*8+lane
            if (lane < 8) {
                int  b      = g * 8 + lane;
                bool active = (s < lenp[g]);
                const float4* pp = (const float4*)(part + w * 288 + lane * 36);
                float4 s4 = pp[0];
#pragma unroll
                for (int jq = 1; jq < 8; jq++) {
                    float4 t = pp[jq];
                    s4.x += t.x; s4.y += t.y; s4.z += t.z; s4.w += t.w;
                }
                float gi = s4.x + g_sm[lane * 36 + 0 * 8 + w] + bias[0];
                float gf = s4.y + g_sm[lane * 36 + 1 * 8 + w] + bias[1];
                float gg = s4.z + g_sm[lane * 36 + 2 * 8 + w] + bias[2];
                float go = s4.w + g_sm[lane * 36 + 3 * 8 + w] + bias[3];
                float i_ = 1.f / (1.f + __expf(-gi));
                float f_ = 1.f / (1.f + __expf(-gf));
                float g_ = tanhf(gg);
                float o_ = 1.f / (1.f + __expf(-go));
                float cn = f_ * creg[g] + i_ * g_;
                float hn = o_ * tanhf(cn);
                if (active) {
                    creg[g] = cn; hreg[g] = hn;
                    if (dir == 0) {
                        out[OUT_OFF + ((size_t)s * BB + b) * 1024 + hc] = hn;
                    } else {
                        int tw = lenp[g] - 1 - s;
                        out[OUT_OFF + ((size_t)tw * BB + b) * 1024 + 512 + hc]
                            = hn;
                    }
                }
                // always publish (frozen or new) h into ring slot s+1
                g_hring[dir][wr][b][hc] = hreg[g];
            }

            // release: all stores above -> visible before counter bump
            __syncthreads();
            if (tid == 0) {
                __threadfence();
                atomicAdd(&g_done[dir][s][g], 1u);
            }
        }
    }

    // finals
    if (lane < 8) {
#pragma unroll
        for (int g = 0; g < 4; g++) {
            int b = g * 8 + lane;
            out[HN_OFF + dir * 16384 + b * HH + hc] = hreg[g];
            out[CN_OFF + dir * 16384 + b * HH + hc] = creg[g];
        }
    }
}

// ---------------- launcher ----------------------------------------------
extern "C" void kernel_launch(void* const* d_in, const int* in_sizes, int n_in,
                              void* d_out, int out_size) {
    const float* cnn  = (const float*)d_in[0];
    const float* fcw  = (const float*)d_in[1];
    const float* fcb  = (const float*)d_in[2];
    const float* h0   = (const float*)d_in[3];
    const float* c0   = (const float*)d_in[4];
    const float* wihf = (const float*)d_in[5];
    const float* whhf = (const float*)d_in[6];
    const float* bihf = (const float*)d_in[7];
    const float* bhhf = (const float*)d_in[8];
    const float* wihb = (const float*)d_in[9];
    const float* whhb = (const float*)d_in[10];
    const float* bihb = (const float*)d_in[11];
    const float* bhhb = (const float*)d_in[12];
    const int* seq_lens = (const int*)d_in[13];
    const int* lookup   = (const int*)d_in[14];
    float* out = (float*)d_out;

    k_reset<<<1, 256>>>(seq_lens, h0, out);
    k_zero<<<16384, 256>>>(out);
    k_prep<<<dim3(2048, 3), 256>>>(fcw, wihf, wihb);
    k_gemm1<<<dim3(8, 8, 32), 128>>>(cnn, fcb, lookup, out + X_OFF);
    k_gemm2<<<dim3(32, 256, 2), 128>>>(out + X_OFF);
    k_scan<<<128, 256>>>(c0, h0, whhf, whhb, bihf, bhhf, bihb, bhhb, out);
}

// round 13
// speedup vs baseline: 1.7569x; 1.2620x over previous
#include <cuda_runtime.h>
#include <cstdint>

// Problem dims
#define TT    512
#define BB    32
#define DD    512
#define HH    512
#define FEAT  2048
#define G4H   2048   // 4*H

// Output layout (fp32, tuple order: out, h_n, c_n, x, lens_s)
#define OUT_OFF  0
#define HN_OFF   16777216
#define CN_OFF   (16777216 + 32768)
#define X_OFF    (16777216 + 65536)
#define LENS_OFF (X_OFF + 8388608)

#define GSZ       (512*32*2048)        // per-direction G size (floats)
#define WCHUNKS   524288               // frag chunks per weight matrix

// ---------------- device scratch ---------------------------------------
__device__ float    g_G[2 * GSZ];          // input-gate preactivations (268MB)
__device__ float    g_hring[2][4][BB][HH]; // h ring buffer, depth 4
__device__ unsigned g_done[2][TT][4];      // per (dir, step, group) counters
__device__ int      g_order[BB];
__device__ int      g_lens[BB];
__device__ uint4    g_wfc[WCHUNKS];        // fc_w   frag-layout (hi/lo tf32)
__device__ uint4    g_wih[2][WCHUNKS];     // w_ih_f / w_ih_b frag-layout

// ---------------- helpers ----------------------------------------------
__device__ __forceinline__ uint32_t f2tf32(float v) {
    uint32_t r;
    asm("cvt.rna.tf32.f32 %0, %1;" : "=r"(r) : "f"(v));
    return r;
}

__device__ __forceinline__ void mma_tf32(float4& c, const uint4& a,
                                         uint32_t b0, uint32_t b1) {
    asm volatile(
        "mma.sync.aligned.m16n8k8.row.col.f32.tf32.tf32.f32 "
        "{%0,%1,%2,%3}, {%4,%5,%6,%7}, {%8,%9}, {%0,%1,%2,%3};"
        : "+f"(c.x), "+f"(c.y), "+f"(c.z), "+f"(c.w)
        : "r"(a.x), "r"(a.y), "r"(a.z), "r"(a.w), "r"(b0), "r"(b1));
}

#define FMA2(acc, a, b) \
    asm("fma.rn.f32x2 %0, %1, %2, %0;" : "+l"(acc) : "l"(a), "l"(b))

__device__ __forceinline__ float sum2(unsigned long long v) {
    float lo, hi;
    asm("mov.b64 {%0,%1}, %2;" : "=f"(lo), "=f"(hi) : "l"(v));
    return lo + hi;
}

__device__ __forceinline__ unsigned long long packf2(float a, float b) {
    unsigned long long u;
    asm("mov.b64 %0, {%1,%2};" : "=l"(u) : "f"(a), "f"(b));
    return u;
}

// ---------------- reset / sort kernel ----------------------------------
__global__ void k_reset(const int* __restrict__ seq_lens,
                        const float* __restrict__ h0,
                        float* __restrict__ out) {
    int tid = threadIdx.x;
    if (tid == 0) {
        unsigned used = 0u;
        for (int pos = 0; pos < BB; pos++) {
            int best = -1, bl = -1;
            for (int i = 0; i < BB; i++) {
                if (used & (1u << i)) continue;
                int L = seq_lens[i];
                if (L > bl) { bl = L; best = i; }
            }
            used |= 1u << best;
            g_order[pos] = best;
            g_lens[pos]  = bl;
            out[LENS_OFF + pos] = (float)bl;
        }
    }
    // zero done counters
    for (int i = tid; i < 2 * TT * 4; i += blockDim.x)
        ((unsigned*)g_done)[i] = 0u;
    // ring slot 0 <- h0
    for (int i = tid; i < 2 * 16384; i += blockDim.x) {
        int dir = i >> 14;
        int r   = i & 16383;
        g_hring[dir][0][r >> 9][r & 511] = h0[i];
    }
}

// ---------------- bulk zero of the `out` region -------------------------
__global__ void __launch_bounds__(256) k_zero(float* __restrict__ out) {
    size_t i = ((size_t)blockIdx.x * 256 + threadIdx.x) * 4;
    *(float4*)&out[OUT_OFF + i] = make_float4(0.f, 0.f, 0.f, 0.f);
}

// ---------------- weight pre-conversion to frag layout ------------------
__global__ void __launch_bounds__(256) k_prep(
    const float* __restrict__ fcw, const float* __restrict__ wihf,
    const float* __restrict__ wihb) {
    int z = blockIdx.y;
    const float* src = (z == 0) ? fcw : ((z == 1) ? wihf : wihb);
    uint4* dst = (z == 0) ? g_wfc : g_wih[z - 1];
    int K     = (z == 0) ? FEAT : DD;
    int nKtm1 = (z == 0) ? 63 : 15;
    int nKtsh = (z == 0) ? 6 : 4;

    int c    = blockIdx.x * 256 + threadIdx.x;
    int lane = c & 31;
    int hl   = (c >> 5) & 1;
    int s    = (c >> 6) & 3;
    int q    = (c >> 8) & 3;
    int tile = c >> 10;
    int qt   = tile & nKtm1;
    int r64  = tile >> nKtsh;
    int g    = lane >> 2, tg = lane & 3;
    int m0   = r64 * 64 + s * 16;
    int kk   = qt * 32 + q * 8 + tg;

    float v0 = src[(size_t)(m0 + g)     * K + kk];
    float v1 = src[(size_t)(m0 + g + 8) * K + kk];
    float v2 = src[(size_t)(m0 + g)     * K + kk + 4];
    float v3 = src[(size_t)(m0 + g + 8) * K + kk + 4];
    uint4 o;
    if (hl == 0) {
        o.x = f2tf32(v0); o.y = f2tf32(v1); o.z = f2tf32(v2); o.w = f2tf32(v3);
    } else {
        o.x = f2tf32(v0 - __uint_as_float(f2tf32(v0)));
        o.y = f2tf32(v1 - __uint_as_float(f2tf32(v1)));
        o.z = f2tf32(v2 - __uint_as_float(f2tf32(v2)));
        o.w = f2tf32(v3 - __uint_as_float(f2tf32(v3)));
    }
    dst[c] = o;
}

// ================= MMA GEMMs (A = weights frag-global, B = data rows) ==
__device__ __forceinline__ void sts_b_convert(uint4* Bsm, const float4* braw,
                                              int r, int qp) {
    int xr = (r & 3) ^ ((r >> 2) & 3);
#pragma unroll
    for (int oo = 0; oo < 2; oo++) {
        float f[8];
        f[0] = braw[oo*2].x;   f[1] = braw[oo*2].y;
        f[2] = braw[oo*2].z;   f[3] = braw[oo*2].w;
        f[4] = braw[oo*2+1].x; f[5] = braw[oo*2+1].y;
        f[6] = braw[oo*2+1].z; f[7] = braw[oo*2+1].w;
        uint32_t hi[8], lo[8];
#pragma unroll
        for (int p = 0; p < 8; p++) {
            hi[p] = f2tf32(f[p]);
            lo[p] = f2tf32(f[p] - __uint_as_float(hi[p]));
        }
        int q = qp * 2 + oo;
        int sbase = q * 256 + r * 4;
#pragma unroll
        for (int t2 = 0; t2 < 4; t2++) {
            uint4 ch;
            ch.x = hi[t2]; ch.y = hi[t2 + 4];
            ch.z = lo[t2]; ch.w = lo[t2 + 4];
            Bsm[sbase + (t2 ^ xr)] = ch;
        }
    }
}

__device__ __forceinline__ void mma_ktile(const uint4* As, const uint4* Bsm,
                                          float4 c[2][4], int wm, int wn,
                                          int lane, int g, int tg) {
#pragma unroll
    for (int q = 0; q < 4; q++) {
        uint4 ah[2], al[2], bq[4];
#pragma unroll
        for (int mi = 0; mi < 2; mi++) {
            int s = wm * 2 + mi;
            ah[mi] = As[((q * 4 + s) * 2 + 0) * 32 + lane];
            al[mi] = As[((q * 4 + s) * 2 + 1) * 32 + lane];
        }
#pragma unroll
        for (int ni = 0; ni < 4; ni++) {
            int rr = wn * 32 + ni * 8 + g;
            int sw = tg ^ (rr & 3) ^ ((rr >> 2) & 3);
            bq[ni] = Bsm[q * 256 + rr * 4 + sw];
        }
#pragma unroll
        for (int mi = 0; mi < 2; mi++)
#pragma unroll
            for (int ni = 0; ni < 4; ni++) {
                mma_tf32(c[mi][ni], ah[mi], bq[ni].x, bq[ni].y);
                mma_tf32(c[mi][ni], ah[mi], bq[ni].z, bq[ni].w);
                mma_tf32(c[mi][ni], al[mi], bq[ni].x, bq[ni].y);
            }
    }
}

// GEMM1: x[t,j,ch] = mask * (cnn[lookup[order[j],t]] @ fc_w^T + fc_b)[ch]
__global__ void __launch_bounds__(128) k_gemm1(
    const float* __restrict__ cnn, const float* __restrict__ fcb,
    const int* __restrict__ lookup, float* __restrict__ xout) {
    __shared__ uint4 As[1024];
    __shared__ uint4 Bsm[1024];
    __shared__ int   simg[64];

    int j   = blockIdx.z;
    int t0  = blockIdx.y * 64;
    int m0  = blockIdx.x * 64;
    int tid = threadIdx.x;
    int len = g_lens[j];

    if (t0 >= len) {
        for (int i = tid; i < 1024; i += 128) {
            int r  = i >> 4;
            int cc = (i & 15) * 4;
            int t  = t0 + r;
            *(float4*)&xout[((size_t)t * BB + j) * DD + m0 + cc] =
                make_float4(0.f, 0.f, 0.f, 0.f);
        }
        return;
    }
    if (tid < 64) simg[tid] = lookup[g_order[j] * TT + t0 + tid];
    __syncthreads();

    int lane = tid & 31;
    int w    = tid >> 5;
    int wm   = w >> 1, wn = w & 1;
    int g    = lane >> 2, tg = lane & 3;
    int r    = tid >> 1, qp = tid & 1;
    size_t brow = (size_t)simg[r] * FEAT;

    float4 c[2][4];
#pragma unroll
    for (int mi = 0; mi < 2; mi++)
#pragma unroll
        for (int ni = 0; ni < 4; ni++) c[mi][ni] = make_float4(0.f,0.f,0.f,0.f);

    uint4  areg[8];
    float4 braw[4];
    {
        const uint4* at = g_wfc + ((size_t)blockIdx.x * 64 + 0) * 1024;
#pragma unroll
        for (int u = 0; u < 8; u++) areg[u] = at[tid + 128 * u];
        int kb = qp * 16;
#pragma unroll
        for (int u = 0; u < 4; u++)
            braw[u] = *(const float4*)&cnn[brow + kb + u * 4];
    }

    for (int kt = 0; kt < 64; kt++) {
        __syncthreads();
#pragma unroll
        for (int u = 0; u < 8; u++) As[tid + 128 * u] = areg[u];
        sts_b_convert(Bsm, braw, r, qp);
        __syncthreads();
        if (kt + 1 < 64) {
            const uint4* at = g_wfc + ((size_t)blockIdx.x * 64 + kt + 1) * 1024;
#pragma unroll
            for (int u = 0; u < 8; u++) areg[u] = at[tid + 128 * u];
            int kb = (kt + 1) * 32 + qp * 16;
#pragma unroll
            for (int u = 0; u < 4; u++)
                braw[u] = *(const float4*)&cnn[brow + kb + u * 4];
        }
        mma_ktile(As, Bsm, c, wm, wn, lane, g, tg);
    }

#pragma unroll
    for (int mi = 0; mi < 2; mi++) {
        int ch  = m0 + wm * 32 + mi * 16 + g;
        float b0 = fcb[ch], b8 = fcb[ch + 8];
#pragma unroll
        for (int ni = 0; ni < 4; ni++) {
            int tA = t0 + wn * 32 + ni * 8 + 2 * tg;
            bool v0 = (tA < len), v1 = (tA + 1 < len);
            size_t r0o = ((size_t)tA * BB + j) * DD;
            size_t r1o = ((size_t)(tA + 1) * BB + j) * DD;
            xout[r0o + ch]     = v0 ? c[mi][ni].x + b0 : 0.f;
            xout[r1o + ch]     = v1 ? c[mi][ni].y + b0 : 0.f;
            xout[r0o + ch + 8] = v0 ? c[mi][ni].z + b8 : 0.f;
            xout[r1o + ch + 8] = v1 ? c[mi][ni].w + b8 : 0.f;
        }
    }
}

// GEMM2: G[dir][j,t,ch] = x[t,j,:] @ w_ih[dir]^T
__global__ void __launch_bounds__(128) k_gemm2(const float* __restrict__ x) {
    __shared__ uint4 As[1024];
    __shared__ uint4 Bsm[1024];

    int dir = blockIdx.z;
    int j   = blockIdx.y >> 3;
    int t0  = (blockIdx.y & 7) * 64;
    int m0  = blockIdx.x * 64;
    int tid = threadIdx.x;
    int len = g_lens[j];
    if (t0 >= len) return;

    int lane = tid & 31;
    int w    = tid >> 5;
    int wm   = w >> 1, wn = w & 1;
    int g    = lane >> 2, tg = lane & 3;
    int r    = tid >> 1, qp = tid & 1;
    size_t brow = ((size_t)(t0 + r) * BB + j) * DD;

    float4 c[2][4];
#pragma unroll
    for (int mi = 0; mi < 2; mi++)
#pragma unroll
        for (int ni = 0; ni < 4; ni++) c[mi][ni] = make_float4(0.f,0.f,0.f,0.f);

    const uint4* wbase = g_wih[dir];
    uint4  areg[8];
    float4 braw[4];
    {
        const uint4* at = wbase + ((size_t)blockIdx.x * 16 + 0) * 1024;
#pragma unroll
        for (int u = 0; u < 8; u++) areg[u] = at[tid + 128 * u];
        int kb = qp * 16;
#pragma unroll
        for (int u = 0; u < 4; u++)
            braw[u] = *(const float4*)&x[brow + kb + u * 4];
    }

    for (int kt = 0; kt < 16; kt++) {
        __syncthreads();
#pragma unroll
        for (int u = 0; u < 8; u++) As[tid + 128 * u] = areg[u];
        sts_b_convert(Bsm, braw, r, qp);
        __syncthreads();
        if (kt + 1 < 16) {
            const uint4* at = wbase + ((size_t)blockIdx.x * 16 + kt + 1) * 1024;
#pragma unroll
            for (int u = 0; u < 8; u++) areg[u] = at[tid + 128 * u];
            int kb = (kt + 1) * 32 + qp * 16;
#pragma unroll
            for (int u = 0; u < 4; u++)
                braw[u] = *(const float4*)&x[brow + kb + u * 4];
        }
        mma_ktile(As, Bsm, c, wm, wn, lane, g, tg);
    }

    float* Gd = g_G + (size_t)dir * GSZ;
#pragma unroll
    for (int mi = 0; mi < 2; mi++) {
        int ch = m0 + wm * 32 + mi * 16 + g;
#pragma unroll
        for (int ni = 0; ni < 4; ni++) {
            int tA = t0 + wn * 32 + ni * 8 + 2 * tg;
            size_t r0o = ((size_t)j * TT + tA) * G4H;
            size_t r1o = ((size_t)j * TT + tA + 1) * G4H;
            Gd[r0o + ch]     = c[mi][ni].x;
            Gd[r1o + ch]     = c[mi][ni].y;
            Gd[r0o + ch + 8] = c[mi][ni].z;
            Gd[r1o + ch + 8] = c[mi][ni].w;
        }
    }
}

// ---------------- persistent scan kernel (v7: pipelined ticks) ----------
// Same protocol/semantics as v6 (R12, passed) with software pipelining:
// poll+prefetch of tick i+1 overlaps tick i's dot. Double-buffered
// h_s/g_sm; ONE __syncthreads per tick. Single-group tail (dep == current
// tick) falls back to v6-style post-release staging.
__global__ void __launch_bounds__(256, 1) k_scan(
    const float* __restrict__ c0, const float* __restrict__ h0,
    const float* __restrict__ whhf, const float* __restrict__ whhb,
    const float* __restrict__ bihf, const float* __restrict__ bhhf,
    const float* __restrict__ bihb, const float* __restrict__ bhhb,
    float* __restrict__ out) {
    __shared__ float h_s[2][8 * 544];
    __shared__ float g_sm[2][8 * 36];
    __shared__ float part[8 * 288];

    int bid  = blockIdx.x;
    int dir  = bid >> 6;
    int ctad = bid & 63;
    int hcb  = ctad * 8;
    int tid  = threadIdx.x;
    int w    = tid >> 5;
    int lane = tid & 31;
    int g4   = lane & 3;
    int ks   = lane >> 2;
    int hc   = hcb + w;

    const float* whh = dir ? whhb : whhf;
    ulonglong2 warr[16];
    {
        const float* wrow = whh + (size_t)(g4 * HH + hc) * HH + ks * 64;
#pragma unroll
        for (int i = 0; i < 16; i++) {
            float4 v = *(const float4*)(wrow + i * 4);
            warr[i].x = packf2(v.x, v.y);
            warr[i].y = packf2(v.z, v.w);
        }
    }
    float bias[4];
    {
        const float* bih = dir ? bihb : bihf;
        const float* bhh = dir ? bhhb : bhhf;
#pragma unroll
        for (int q = 0; q < 4; q++)
            bias[q] = bih[q * HH + hc] + bhh[q * HH + hc];
    }

    float creg[4], hreg[4];
    int   lenp[4];
    if (lane < 8) {
#pragma unroll
        for (int g = 0; g < 4; g++) {
            int b = g * 8 + lane;
            lenp[g] = g_lens[b];
            creg[g] = c0[dir * 16384 + b * HH + hc];
            hreg[g] = h0[dir * 16384 + b * HH + hc];
        }
    }

    // G loader role
    int lb  = tid >> 5;
    int lg  = (tid & 31) >> 3;
    int lch = tid & 7;
    const float* Gd = g_G + (size_t)dir * GSZ;
    int lenG4[4];
#pragma unroll
    for (int g = 0; g < 4; g++) lenG4[g] = g_lens[g * 8 + lb];

    int glen[4];
#pragma unroll
    for (int g = 0; g < 4; g++) glen[g] = g_lens[g * 8];
    int maxlen = glen[0];

    // ---- prologue: stage tick (0,0) into buf 0 ----
    {
        const float* hin = &g_hring[dir][0][0][0];
#pragma unroll
        for (int i = 0; i < 4; i++) {
            int idx = tid + 256 * i;
            float4 v = __ldcg((const float4*)&hin[idx * 4]);
            int b = idx >> 7;
            int k = (idx & 127) * 4;
            *(float4*)&h_s[0][b * 544 + (k >> 6) * 68 + (k & 63)] = v;
        }
        float gv = 0.f;
        if (0 < lenG4[0]) {
            int tt0 = dir ? (lenG4[0] - 1) : 0;
            gv = __ldg(&Gd[((size_t)lb * TT + tt0) * G4H + lg * HH + hcb + lch]);
        }
        g_sm[0][lb * 36 + lg * 8 + lch] = gv;
    }
    __syncthreads();

    int s = 0, g = 0, buf = 0;
    for (;;) {
        // next tick in the global sequence
        int ns = s, ng = g + 1;
        if (ng == 4 || ns >= glen[ng]) { ns = s + 1; ng = 0; }
        bool have_next = (ns < maxlen);
        bool can_pre   = have_next && !(ns == s + 1 && g == 0);

        // ---- poll + prefetch next tick (overlaps the dot) ----
        float4 hpre[4];
        float  gpre = 0.f;
        if (can_pre) {
            if (ns > 0) {
                const unsigned* fp = &g_done[dir][ns - 1][ng];
                unsigned v;
                for (;;) {
                    asm volatile("ld.global.cg.u32 %0, [%1];"
                                 : "=r"(v) : "l"(fp));
                    if (v >= 64u) break;
                    __nanosleep(20);
                }
            }
            const float* hin = &g_hring[dir][ns & 3][ng * 8][0];
#pragma unroll
            for (int i = 0; i < 4; i++) {
                int idx = tid + 256 * i;
                hpre[i] = __ldcg((const float4*)&hin[idx * 4]);
            }
            if (ns < lenG4[ng]) {
                int bG = ng * 8 + lb;
                int tt = dir ? (lenG4[ng] - 1 - ns) : ns;
                gpre = __ldg(&Gd[((size_t)bG * TT + tt) * G4H +
                                 lg * HH + hcb + lch]);
            }
        }

        // ---- dot from h_s[buf] ----
        const float* hbase = &h_s[buf][0] + ks * 68;
        float* psts = part + w * 288 + lane;
#pragma unroll 2
        for (int b = 0; b < 8; b++) {
            const ulonglong2* hp = (const ulonglong2*)(hbase + b * 544);
            unsigned long long a0 = 0, a1 = 0;
#pragma unroll
            for (int jj = 0; jj < 16; jj++) {
                ulonglong2 h2 = hp[jj];
                FMA2(a0, h2.x, warr[jj].x);
                FMA2(a1, h2.y, warr[jj].y);
            }
            psts[b * 36] = sum2(a0) + sum2(a1);
        }
        __syncwarp();

        // ---- pointwise: thread (w, lane<8) for batch b = g*8+lane ----
        if (lane < 8) {
            int  b      = g * 8 + lane;
            bool active = (s < lenp[g]);
            const float4* pp = (const float4*)(part + w * 288 + lane * 36);
            float4 s4 = pp[0];
#pragma unroll
            for (int jq = 1; jq < 8; jq++) {
                float4 t = pp[jq];
                s4.x += t.x; s4.y += t.y; s4.z += t.z; s4.w += t.w;
            }
            float gi = s4.x + g_sm[buf][lane * 36 + 0 * 8 + w] + bias[0];
            float gf = s4.y + g_sm[buf][lane * 36 + 1 * 8 + w] + bias[1];
            float gg = s4.z + g_sm[buf][lane * 36 + 2 * 8 + w] + bias[2];
            float go = s4.w + g_sm[buf][lane * 36 + 3 * 8 + w] + bias[3];
            float i_ = 1.f / (1.f + __expf(-gi));
            float f_ = 1.f / (1.f + __expf(-gf));
            float g_ = tanhf(gg);
            float o_ = 1.f / (1.f + __expf(-go));
            float cn = f_ * creg[g] + i_ * g_;
            float hn = o_ * tanhf(cn);
            if (active) {
                creg[g] = cn; hreg[g] = hn;
                if (dir == 0) {
                    out[OUT_OFF + ((size_t)s * BB + b) * 1024 + hc] = hn;
                } else {
                    int tw = lenp[g] - 1 - s;
                    out[OUT_OFF + ((size_t)tw * BB + b) * 1024 + 512 + hc] = hn;
                }
            }
            g_hring[dir][(s + 1) & 3][b][hc] = hreg[g];
        }

        // ---- stage prefetched data into the other buffer ----
        if (can_pre) {
#pragma unroll
            for (int i = 0; i < 4; i++) {
                int idx = tid + 256 * i;
                int b = idx >> 7;
                int k = (idx & 127) * 4;
                *(float4*)&h_s[buf ^ 1][b * 544 + (k >> 6) * 68 + (k & 63)]
                    = hpre[i];
            }
            g_sm[buf ^ 1][lb * 36 + lg * 8 + lch] = gpre;
        }

        // ---- release current tick (proven pattern) ----
        __syncthreads();
        if (tid == 0) {
            __threadfence();
            atomicAdd(&g_done[dir][s][g], 1u);
        }

        if (!have_next) break;

        // ---- fallback staging when dep == current tick (1-group tail) ----
        if (!can_pre) {
            const unsigned* fp = &g_done[dir][ns - 1][ng];
            unsigned v;
            for (;;) {
                asm volatile("ld.global.cg.u32 %0, [%1];" : "=r"(v) : "l"(fp));
                if (v >= 64u) break;
                __nanosleep(20);
            }
            const float* hin = &g_hring[dir][ns & 3][ng * 8][0];
#pragma unroll
            for (int i = 0; i < 4; i++) {
                int idx = tid + 256 * i;
                float4 hv = __ldcg((const float4*)&hin[idx * 4]);
                int b = idx >> 7;
                int k = (idx & 127) * 4;
                *(float4*)&h_s[buf ^ 1][b * 544 + (k >> 6) * 68 + (k & 63)]
                    = hv;
            }
            float gv = 0.f;
            if (ns < lenG4[ng]) {
                int bG = ng * 8 + lb;
                int tt = dir ? (lenG4[ng] - 1 - ns) : ns;
                gv = __ldg(&Gd[((size_t)bG * TT + tt) * G4H +
                               lg * HH + hcb + lch]);
            }
            g_sm[buf ^ 1][lb * 36 + lg * 8 + lch] = gv;
            __syncthreads();
        }

        s = ns; g = ng; buf ^= 1;
    }

    // finals
    if (lane < 8) {
#pragma unroll
        for (int g = 0; g < 4; g++) {
            int b = g * 8 + lane;
            out[HN_OFF + dir * 16384 + b * HH + hc] = hreg[g];
            out[CN_OFF + dir * 16384 + b * HH + hc] = creg[g];
        }
    }
}

// ---------------- launcher ----------------------------------------------
extern "C" void kernel_launch(void* const* d_in, const int* in_sizes, int n_in,
                              void* d_out, int out_size) {
    const float* cnn  = (const float*)d_in[0];
    const float* fcw  = (const float*)d_in[1];
    const float* fcb  = (const float*)d_in[2];
    const float* h0   = (const float*)d_in[3];
    const float* c0   = (const float*)d_in[4];
    const float* wihf = (const float*)d_in[5];
    const float* whhf = (const float*)d_in[6];
    const float* bihf = (const float*)d_in[7];
    const float* bhhf = (const float*)d_in[8];
    const float* wihb = (const float*)d_in[9];
    const float* whhb = (const float*)d_in[10];
    const float* bihb = (const float*)d_in[11];
    const float* bhhb = (const float*)d_in[12];
    const int* seq_lens = (const int*)d_in[13];
    const int* lookup   = (const int*)d_in[14];
    float* out = (float*)d_out;

    k_reset<<<1, 256>>>(seq_lens, h0, out);
    k_zero<<<16384, 256>>>(out);
    k_prep<<<dim3(2048, 3), 256>>>(fcw, wihf, wihb);
    k_gemm1<<<dim3(8, 8, 32), 128>>>(cnn, fcb, lookup, out + X_OFF);
    k_gemm2<<<dim3(32, 256, 2), 128>>>(out + X_OFF);
    k_scan<<<128, 256>>>(c0, h0, whhf, whhb, bihf, bhhf, bihb, bhhb, out);
}